// round 17
// baseline (speedup 1.0000x reference)
#include <cuda_runtime.h>
#include <math.h>
#include <stdint.h>

// Problem constants
#define BSZ   2
#define SEQ   2048
#define EMB   2048
#define NH    32
#define HD    64
#define KVHN  8
#define KVD   512
#define GRP   4
#define MTOT  (BSZ*SEQ)   // 4096

// Scratch — device globals, referenced ONLY inside device code.
__device__ __align__(16) float    g_q [MTOT * EMB];
// pre-split bf16 hi/lo operands
__device__ __align__(16) uint16_t g_xh[MTOT * EMB],  g_xl[MTOT * EMB];
__device__ __align__(16) uint16_t g_wqh[EMB * EMB],  g_wql[EMB * EMB];
__device__ __align__(16) uint16_t g_wkh[EMB * KVD],  g_wkl[EMB * KVD];
__device__ __align__(16) uint16_t g_wvh[EMB * KVD],  g_wvl[EMB * KVD];
__device__ __align__(16) uint16_t g_woh[EMB * EMB],  g_wol[EMB * EMB];
__device__ __align__(16) uint16_t g_kh [MTOT * KVD], g_kl [MTOT * KVD];
__device__ __align__(16) uint16_t g_vh [MTOT * KVD], g_vl [MTOT * KVD];
__device__ __align__(16) uint16_t g_ah [MTOT * EMB], g_al [MTOT * EMB];

// ---------------------------------------------------------------------------
// PTX helpers
// ---------------------------------------------------------------------------
__device__ __forceinline__ uint32_t smem_u32(const void* p) {
    return (uint32_t)__cvta_generic_to_shared(p);
}
__device__ __forceinline__ void cp_async16(uint32_t dst, const void* src) {
    asm volatile("cp.async.cg.shared.global [%0], [%1], 16;" :: "r"(dst), "l"(src));
}
__device__ __forceinline__ void cp_commit() {
    asm volatile("cp.async.commit_group;");
}
template<int N>
__device__ __forceinline__ void cp_wait() {
    asm volatile("cp.async.wait_group %0;" :: "n"(N));
}
__device__ __forceinline__ uint32_t pack_bf16x2(float v0, float v1) {
    uint32_t r;
    asm("cvt.rn.bf16x2.f32 %0, %1, %2;" : "=r"(r) : "f"(v1), "f"(v0));
    return r;
}
__device__ __forceinline__ void split_pair(float v0, float v1, uint32_t& hi, uint32_t& lo) {
    hi = pack_bf16x2(v0, v1);
    float h0 = __uint_as_float(hi << 16);
    float h1 = __uint_as_float(hi & 0xffff0000u);
    lo = pack_bf16x2(v0 - h0, v1 - h1);
}
__device__ __forceinline__ void mma_bf16(float* c, const uint32_t* a, const uint32_t* b) {
    asm volatile(
        "mma.sync.aligned.m16n8k16.row.col.f32.bf16.bf16.f32 "
        "{%0,%1,%2,%3},{%4,%5,%6,%7},{%8,%9},{%0,%1,%2,%3};"
        : "+f"(c[0]), "+f"(c[1]), "+f"(c[2]), "+f"(c[3])
        : "r"(a[0]), "r"(a[1]), "r"(a[2]), "r"(a[3]), "r"(b[0]), "r"(b[1]));
}
__device__ __forceinline__ void ldsm4(uint32_t* r, uint32_t addr) {
    asm volatile("ldmatrix.sync.aligned.m8n8.x4.shared.b16 {%0,%1,%2,%3}, [%4];"
        : "=r"(r[0]), "=r"(r[1]), "=r"(r[2]), "=r"(r[3]) : "r"(addr));
}
__device__ __forceinline__ void ldsm2(uint32_t* r, uint32_t addr) {
    asm volatile("ldmatrix.sync.aligned.m8n8.x2.shared.b16 {%0,%1}, [%2];"
        : "=r"(r[0]), "=r"(r[1]) : "r"(addr));
}
__device__ __forceinline__ void ldsm2t(uint32_t* r, uint32_t addr) {
    asm volatile("ldmatrix.sync.aligned.m8n8.x2.trans.shared.b16 {%0,%1}, [%2];"
        : "=r"(r[0]), "=r"(r[1]) : "r"(addr));
}

// ---------------------------------------------------------------------------
// Pre-pass: fp32 -> bf16 hi/lo split for x and all weights. Grid-stride.
// blockIdx.y selects tensor: 0=x 1=Wq 2=Wk 3=Wv 4=Wo.
// ---------------------------------------------------------------------------
__global__ __launch_bounds__(256)
void k_conv(const float* __restrict__ x,  const float* __restrict__ wq,
            const float* __restrict__ wk, const float* __restrict__ wv,
            const float* __restrict__ wo)
{
    const float* s; uint16_t *dh, *dl; int n4;
    switch (blockIdx.y) {
        case 0: s = x;  dh = g_xh;  dl = g_xl;  n4 = MTOT * EMB / 4; break;
        case 1: s = wq; dh = g_wqh; dl = g_wql; n4 = EMB * EMB / 4;  break;
        case 2: s = wk; dh = g_wkh; dl = g_wkl; n4 = EMB * KVD / 4;  break;
        case 3: s = wv; dh = g_wvh; dl = g_wvl; n4 = EMB * KVD / 4;  break;
        default:s = wo; dh = g_woh; dl = g_wol; n4 = EMB * EMB / 4;  break;
    }
    for (int i = blockIdx.x * blockDim.x + threadIdx.x; i < n4;
         i += gridDim.x * blockDim.x) {
        float4 v = *(const float4*)(s + (size_t)i * 4);
        uint32_t h01, l01, h23, l23;
        split_pair(v.x, v.y, h01, l01);
        split_pair(v.z, v.w, h23, l23);
        *(uint2*)(dh + (size_t)i * 4) = make_uint2(h01, h23);
        *(uint2*)(dl + (size_t)i * 4) = make_uint2(l01, l23);
    }
}

// ---------------------------------------------------------------------------
// Pure-bf16 tensor-core GEMM: pre-split hi/lo operands, cp.async 3-stage
// pipeline, LDSM + mma (R16-proven mma section). CTA 128x128, BK=32, 256 thr.
// MODE 0: fp32 epilogue to C. MODE 1: bf16 hi/lo epilogue to Ch/Cl.
// ---------------------------------------------------------------------------
#define BM 128
#define BN 128
#define BK 32
#define AH_O 0
#define AL_O 5120
#define BH_O 10240
#define BL_O 14592
#define STG  18944                       // stage stride, uint16 elems
#define SMEM_GEMM (3 * STG * 2)          // 113664 B
#define GTHREADS 256

template<int MODE>
__device__ __forceinline__
void gemm_bf(const uint16_t* __restrict__ Ahg, const uint16_t* __restrict__ Alg,
             const uint16_t* __restrict__ Bhg, const uint16_t* __restrict__ Blg,
             float* __restrict__ C, uint16_t* __restrict__ Ch, uint16_t* __restrict__ Cl,
             int N, int K, int bx)
{
    extern __shared__ char smraw[];
    uint16_t* sm = (uint16_t*)smraw;
    const uint32_t smB = smem_u32(sm);

    const int tid  = threadIdx.x;
    const int lane = tid & 31;
    const int wid  = tid >> 5;
    const int wm   = wid & 1;
    const int wn   = wid >> 1;
    const int m0   = blockIdx.y * BM;
    const int n0   = bx * BN;
    const int lg   = lane >> 2;
    const int lt   = lane & 3;

    // LDSM lane-address components (byte offsets)
    const int rowA = ((lane >> 3) & 1) * 8 + (lane & 7);
    const int colA = (lane >> 4) * 8;
    const uint32_t aLane = (uint32_t)(rowA * 40 + colA) * 2;
    const uint32_t bLane = (uint32_t)((lane & 15) * 136) * 2;

    // loader lane coordinates
    const int arA = tid >> 2, acA = (tid & 3) * 8;          // A: 128 rows x 4 c16 (x2 iters)
    const int brB = tid >> 4, bcB = (tid & 15) * 8;         // B: 32 rows x 16 c16 (x2 iters)

    auto loadA = [&](int st, int kc) {
        #pragma unroll
        for (int i = 0; i < 2; i++) {
            int r = arA + i * 64;
            uint32_t d = smB + (uint32_t)(st * STG + r * 40 + acA) * 2;
            const uint16_t* sh = Ahg + (size_t)(m0 + r) * K + kc * BK + acA;
            const uint16_t* sl = Alg + (size_t)(m0 + r) * K + kc * BK + acA;
            cp_async16(d + AH_O * 2, sh);
            cp_async16(d + AL_O * 2, sl);
        }
    };
    auto loadB = [&](int st, int kc) {
        #pragma unroll
        for (int i = 0; i < 2; i++) {
            int r = brB + i * 16;
            uint32_t d = smB + (uint32_t)(st * STG + r * 136 + bcB) * 2;
            const uint16_t* sh = Bhg + (size_t)(kc * BK + r) * N + n0 + bcB;
            const uint16_t* sl = Blg + (size_t)(kc * BK + r) * N + n0 + bcB;
            cp_async16(d + BH_O * 2, sh);
            cp_async16(d + BL_O * 2, sl);
        }
    };

    float acc[4][4][4] = {};
    const int nk = K / BK;

    loadA(0, 0); loadB(0, 0); cp_commit();
    loadA(1, 1); loadB(1, 1); cp_commit();

    for (int c = 0; c < nk; c++) {
        if (c < nk - 1) cp_wait<1>(); else cp_wait<0>();
        __syncthreads();
        if (c + 2 < nk) {
            int st = (c + 2) % 3;
            loadA(st, c + 2); loadB(st, c + 2); cp_commit();
        }

        const int cur = c % 3;
        const uint32_t ahB = smB + (cur * STG + AH_O) * 2 + (wm * 64 * 40) * 2 + aLane;
        const uint32_t alB = smB + (cur * STG + AL_O) * 2 + (wm * 64 * 40) * 2 + aLane;
        const uint32_t bhB = smB + (cur * STG + BH_O) * 2 + (wn * 32) * 2 + bLane;
        const uint32_t blB = smB + (cur * STG + BL_O) * 2 + (wn * 32) * 2 + bLane;

        #pragma unroll
        for (int ks = 0; ks < 2; ks++) {
            const int k = ks * 16;
            uint32_t ah[4][4], al[4][4];
            #pragma unroll
            for (int mi = 0; mi < 4; mi++) {
                uint32_t off = (uint32_t)(mi * 16 * 40 + k) * 2;
                ldsm4(ah[mi], ahB + off);
                ldsm4(al[mi], alB + off);
            }
            #pragma unroll
            for (int ni = 0; ni < 4; ni++) {
                uint32_t off = (uint32_t)(k * 136 + ni * 8) * 2;
                uint32_t bh[2], bl[2];
                ldsm2t(bh, bhB + off);
                ldsm2t(bl, blB + off);
                #pragma unroll
                for (int mi = 0; mi < 4; mi++) {
                    mma_bf16(acc[mi][ni], ah[mi], bh);
                    mma_bf16(acc[mi][ni], ah[mi], bl);
                    mma_bf16(acc[mi][ni], al[mi], bh);
                }
            }
        }
    }

    // ---- epilogue ----
    #pragma unroll
    for (int mi = 0; mi < 4; mi++) {
        #pragma unroll
        for (int ni = 0; ni < 4; ni++) {
            int row = m0 + wm * 64 + mi * 16 + lg;
            int col = n0 + wn * 32 + ni * 8 + 2 * lt;
            if (MODE == 0) {
                *(float2*)(C + (size_t)row * N + col) =
                    make_float2(acc[mi][ni][0], acc[mi][ni][1]);
                *(float2*)(C + (size_t)(row + 8) * N + col) =
                    make_float2(acc[mi][ni][2], acc[mi][ni][3]);
            } else {
                uint32_t h, l;
                split_pair(acc[mi][ni][0], acc[mi][ni][1], h, l);
                *(uint32_t*)(Ch + (size_t)row * N + col) = h;
                *(uint32_t*)(Cl + (size_t)row * N + col) = l;
                split_pair(acc[mi][ni][2], acc[mi][ni][3], h, l);
                *(uint32_t*)(Ch + (size_t)(row + 8) * N + col) = h;
                *(uint32_t*)(Cl + (size_t)(row + 8) * N + col) = l;
            }
        }
    }
}

// Fused Q/K/V projection: grid.x 0..15 -> Q (fp32 out), 16..19 -> K, 20..23 -> V
__global__ __launch_bounds__(GTHREADS)
void k_proj_qkv()
{
    int bx = blockIdx.x;
    if (bx < 16)
        gemm_bf<0>(g_xh, g_xl, g_wqh, g_wql, g_q, 0, 0, EMB, EMB, bx);
    else if (bx < 20)
        gemm_bf<1>(g_xh, g_xl, g_wkh, g_wkl, 0, g_kh, g_kl, KVD, EMB, bx - 16);
    else
        gemm_bf<1>(g_xh, g_xl, g_wvh, g_wvl, 0, g_vh, g_vl, KVD, EMB, bx - 20);
}
__global__ __launch_bounds__(GTHREADS)
void k_out_proj(float* __restrict__ out)
{
    gemm_bf<0>(g_ah, g_al, g_woh, g_wol, out, 0, 0, EMB, EMB, blockIdx.x);
}

// ---------------------------------------------------------------------------
// Tensor-core causal GQA flash attention: K/V arrive pre-split bf16 hi/lo
// (raw copies into smem), Q fp32 (scaled+split once). Output written as
// bf16 hi/lo for the out-projection. Grid (SEQ/64, NH, BSZ), 128 threads.
// ---------------------------------------------------------------------------
#define PK 72   // bf16 row pitch (144 B)

__global__ __launch_bounds__(128)
void attn_tc()
{
    __shared__ uint16_t sKh[64][PK], sKl[64][PK];
    __shared__ uint16_t sVh[64][PK], sVl[64][PK];

    const int qt = blockIdx.x, h = blockIdx.y, b = blockIdx.z;
    const int kvh = h >> 2;
    const int tid = threadIdx.x;
    const int w = tid >> 5, lane = tid & 31;
    const int lg = lane >> 2, lt = lane & 3;
    const int q0 = qt * 64;
    const int qrow = q0 + w * 16;
    const float qscale = 0.125f * 1.44269504f;

    const uint32_t kLane = (uint32_t)((lane & 7) * PK + ((lane >> 3) & 1) * 8) * 2;
    const uint32_t vLane = (uint32_t)((lane & 15) * PK) * 2;
    const uint32_t kHb = smem_u32(sKh) + kLane;
    const uint32_t kLb = smem_u32(sKl) + kLane;
    const uint32_t vHb = smem_u32(sVh) + vLane;
    const uint32_t vLb = smem_u32(sVl) + vLane;

    uint32_t qh[4][4], ql[4][4];
    {
        const float* qp = g_q + (size_t)(b * SEQ + qrow) * EMB + h * HD;
        #pragma unroll
        for (int ks = 0; ks < 4; ks++) {
            int d0 = ks * 16 + 2 * lt;
            float2 v00 = *(const float2*)(qp + (size_t)lg * EMB + d0);
            float2 v10 = *(const float2*)(qp + (size_t)(lg + 8) * EMB + d0);
            float2 v01 = *(const float2*)(qp + (size_t)lg * EMB + d0 + 8);
            float2 v11 = *(const float2*)(qp + (size_t)(lg + 8) * EMB + d0 + 8);
            split_pair(v00.x * qscale, v00.y * qscale, qh[ks][0], ql[ks][0]);
            split_pair(v10.x * qscale, v10.y * qscale, qh[ks][1], ql[ks][1]);
            split_pair(v01.x * qscale, v01.y * qscale, qh[ks][2], ql[ks][2]);
            split_pair(v11.x * qscale, v11.y * qscale, qh[ks][3], ql[ks][3]);
        }
    }

    float m_lo = -1e30f, m_hi = -1e30f;
    float l_lo = 0.f, l_hi = 0.f;
    float o[8][4] = {};

    for (int kt = 0; kt <= qt; kt++) {
        const int k0 = kt * 64;
        __syncthreads();
        // fill K/V tiles: raw bf16 hi/lo copies (no conversion)
        #pragma unroll
        for (int i = 0; i < 4; i++) {
            int idx = tid + i * 128;
            int r = idx >> 3, c8 = (idx & 7) * 8;
            size_t base = (size_t)(b * SEQ + k0 + r) * KVD + kvh * HD + c8;
            *(uint4*)&sKh[r][c8] = *(const uint4*)(g_kh + base);
            *(uint4*)&sKl[r][c8] = *(const uint4*)(g_kl + base);
            *(uint4*)&sVh[r][c8] = *(const uint4*)(g_vh + base);
            *(uint4*)&sVl[r][c8] = *(const uint4*)(g_vl + base);
        }
        __syncthreads();

        float s[8][4] = {};
        #pragma unroll
        for (int ks = 0; ks < 4; ks++) {
            #pragma unroll
            for (int nb = 0; nb < 8; nb++) {
                uint32_t off = (uint32_t)(nb * 8 * PK + ks * 16) * 2;
                uint32_t bh[2], bl[2];
                ldsm2(bh, kHb + off);
                ldsm2(bl, kLb + off);
                mma_bf16(s[nb], qh[ks], bh);
                mma_bf16(s[nb], qh[ks], bl);
                mma_bf16(s[nb], ql[ks], bh);
            }
        }

        if (kt == qt) {
            #pragma unroll
            for (int nb = 0; nb < 8; nb++) {
                int col = k0 + nb * 8 + 2 * lt;
                int rlo = qrow + lg, rhi = qrow + lg + 8;
                if (col     > rlo) s[nb][0] = -1e30f;
                if (col + 1 > rlo) s[nb][1] = -1e30f;
                if (col     > rhi) s[nb][2] = -1e30f;
                if (col + 1 > rhi) s[nb][3] = -1e30f;
            }
        }

        float tm_lo = -1e30f, tm_hi = -1e30f;
        #pragma unroll
        for (int nb = 0; nb < 8; nb++) {
            tm_lo = fmaxf(tm_lo, fmaxf(s[nb][0], s[nb][1]));
            tm_hi = fmaxf(tm_hi, fmaxf(s[nb][2], s[nb][3]));
        }
        #pragma unroll
        for (int off = 1; off <= 2; off <<= 1) {
            tm_lo = fmaxf(tm_lo, __shfl_xor_sync(0xffffffffu, tm_lo, off));
            tm_hi = fmaxf(tm_hi, __shfl_xor_sync(0xffffffffu, tm_hi, off));
        }
        float mn_lo = fmaxf(m_lo, tm_lo);
        float mn_hi = fmaxf(m_hi, tm_hi);
        float sc_lo = exp2f(m_lo - mn_lo);
        float sc_hi = exp2f(m_hi - mn_hi);
        m_lo = mn_lo; m_hi = mn_hi;

        float ps_lo = 0.f, ps_hi = 0.f;
        #pragma unroll
        for (int nb = 0; nb < 8; nb++) {
            s[nb][0] = exp2f(s[nb][0] - mn_lo);
            s[nb][1] = exp2f(s[nb][1] - mn_lo);
            s[nb][2] = exp2f(s[nb][2] - mn_hi);
            s[nb][3] = exp2f(s[nb][3] - mn_hi);
            ps_lo += s[nb][0] + s[nb][1];
            ps_hi += s[nb][2] + s[nb][3];
        }
        l_lo = l_lo * sc_lo + ps_lo;
        l_hi = l_hi * sc_hi + ps_hi;
        #pragma unroll
        for (int nbd = 0; nbd < 8; nbd++) {
            o[nbd][0] *= sc_lo; o[nbd][1] *= sc_lo;
            o[nbd][2] *= sc_hi; o[nbd][3] *= sc_hi;
        }

        #pragma unroll
        for (int kb = 0; kb < 4; kb++) {
            uint32_t ph[4], pl[4];
            split_pair(s[2*kb][0],     s[2*kb][1],     ph[0], pl[0]);
            split_pair(s[2*kb][2],     s[2*kb][3],     ph[1], pl[1]);
            split_pair(s[2*kb + 1][0], s[2*kb + 1][1], ph[2], pl[2]);
            split_pair(s[2*kb + 1][2], s[2*kb + 1][3], ph[3], pl[3]);
            #pragma unroll
            for (int nbd = 0; nbd < 8; nbd++) {
                uint32_t off = (uint32_t)(kb * 16 * PK + nbd * 8) * 2;
                uint32_t vh[2], vl[2];
                ldsm2t(vh, vHb + off);
                ldsm2t(vl, vLb + off);
                mma_bf16(o[nbd], ph, vh);
                mma_bf16(o[nbd], ph, vl);
                mma_bf16(o[nbd], pl, vh);
            }
        }
    }

    // ---- finalize: normalize, split to bf16 hi/lo for out-projection ----
    #pragma unroll
    for (int off = 1; off <= 2; off <<= 1) {
        l_lo += __shfl_xor_sync(0xffffffffu, l_lo, off);
        l_hi += __shfl_xor_sync(0xffffffffu, l_hi, off);
    }
    float inv_lo = 1.0f / l_lo, inv_hi = 1.0f / l_hi;
    #pragma unroll
    for (int nbd = 0; nbd < 8; nbd++) {
        int dcol = nbd * 8 + 2 * lt;
        size_t i0 = (size_t)(b * SEQ + qrow + lg) * EMB + h * HD + dcol;
        size_t i1 = (size_t)(b * SEQ + qrow + lg + 8) * EMB + h * HD + dcol;
        uint32_t hh, ll;
        split_pair(o[nbd][0] * inv_lo, o[nbd][1] * inv_lo, hh, ll);
        *(uint32_t*)(g_ah + i0) = hh;
        *(uint32_t*)(g_al + i0) = ll;
        split_pair(o[nbd][2] * inv_hi, o[nbd][3] * inv_hi, hh, ll);
        *(uint32_t*)(g_ah + i1) = hh;
        *(uint32_t*)(g_al + i1) = ll;
    }
}

// ---------------------------------------------------------------------------
extern "C" void kernel_launch(void* const* d_in, const int* in_sizes, int n_in,
                              void* d_out, int out_size)
{
    const float* x  = (const float*)d_in[0];
    const float* Wq = (const float*)d_in[1];
    const float* Wk = (const float*)d_in[2];
    const float* Wv = (const float*)d_in[3];
    const float* Wo = (const float*)d_in[4];
    float* out = (float*)d_out;

    cudaFuncSetAttribute(k_proj_qkv, cudaFuncAttributeMaxDynamicSharedMemorySize, SMEM_GEMM);
    cudaFuncSetAttribute(k_out_proj, cudaFuncAttributeMaxDynamicSharedMemorySize, SMEM_GEMM);

    k_conv<<<dim3(256, 5), 256>>>(x, Wq, Wk, Wv, Wo);
    k_proj_qkv<<<dim3(24, MTOT / BM), GTHREADS, SMEM_GEMM>>>();
    attn_tc<<<dim3(SEQ / 64, NH, BSZ), 128>>>();
    k_out_proj<<<dim3(EMB / BN, MTOT / BM), GTHREADS, SMEM_GEMM>>>(out);
}